// round 8
// baseline (speedup 1.0000x reference)
#include <cuda_runtime.h>

// ============================================================================
// SGNN: out = relu( 0.5*(softmax(p p^T) @ x + x) @ W3^T + b3 )
// where p = x @ (W2 W1)^T + (W2 b1 + b2).
//
// softmax rows sum to 1, R = softmax + I => rowsum(R)=2 => D^{-1/2} R D^{-1/2}
// = R/2 exactly. Flash-attention streaming softmax (Q=K=p, V=x), residual
// 0.5*x, fused output projection + relu. The 4096x4096 adjacency is never
// materialized.
//
// R6: fix the mangled FFMA2 statement in p_kernel's W_eff loop (row 3 was
// computing aw += aw*aw). Everything else identical to R5.
// ============================================================================

#define LDT 68   // padded smem row stride (floats)

static constexpr int BATCH = 4;
static constexpr int NTOK  = 4096;
static constexpr int FDIM  = 64;

__device__ float g_p[BATCH * NTOK * FDIM];   // 4 MB scratch, L2-resident

using u64 = unsigned long long;

// ---- packed f32x2 helpers --------------------------------------------------
__device__ __forceinline__ u64 pk2(float x, float y) {
    u64 r; asm("mov.b64 %0, {%1, %2};" : "=l"(r) : "f"(x), "f"(y)); return r;
}
__device__ __forceinline__ u64 dup2(float x) {
    u64 r; asm("mov.b64 %0, {%1, %1};" : "=l"(r) : "f"(x)); return r;
}
__device__ __forceinline__ void fma2(u64& d, u64 a, u64 b) {
    asm("fma.rn.f32x2 %0, %1, %2, %0;" : "+l"(d) : "l"(a), "l"(b));
}
__device__ __forceinline__ void mul2(u64& d, u64 a) {
    asm("mul.rn.f32x2 %0, %0, %1;" : "+l"(d) : "l"(a));
}
__device__ __forceinline__ float2 up2(u64 v) {
    float2 f; asm("mov.b64 {%0, %1}, %2;" : "=f"(f.x), "=f"(f.y) : "l"(v)); return f;
}

// ---- tile loaders: 64x64 fp32, 256 threads, coalesced float4 ---------------
// s[k][n] = g[n][k]
__device__ __forceinline__ void load_tile_T(const float* __restrict__ g,
                                            float* __restrict__ s) {
    int t = threadIdx.x;
#pragma unroll
    for (int i = 0; i < 4; i++) {
        int idx = t + i * 256;
        int n   = idx >> 4;
        int k4  = (idx & 15) << 2;
        float4 v = *reinterpret_cast<const float4*>(g + n * 64 + k4);
        s[(k4 + 0) * LDT + n] = v.x;
        s[(k4 + 1) * LDT + n] = v.y;
        s[(k4 + 2) * LDT + n] = v.z;
        s[(k4 + 3) * LDT + n] = v.w;
    }
}
// s[n][k] = g[n][k]
__device__ __forceinline__ void load_tile_N(const float* __restrict__ g,
                                            float* __restrict__ s) {
    int t = threadIdx.x;
#pragma unroll
    for (int i = 0; i < 4; i++) {
        int idx = t + i * 256;
        int n   = idx >> 4;
        int k4  = (idx & 15) << 2;
        *reinterpret_cast<float4*>(s + n * LDT + k4) =
            *reinterpret_cast<const float4*>(g + n * 64 + k4);
    }
}

// ----------------------------------------------------------------------------
// Kernel 1: fused  W_eff = W2@W1, b_eff = W2@b1+b2  (redundant per block) then
// p = x @ W_eff^T + b_eff.   grid = 256, block = 256, 4x4 microtile
// ----------------------------------------------------------------------------
__global__ __launch_bounds__(256) void p_kernel(
    const float* __restrict__ x,
    const float* __restrict__ W1, const float* __restrict__ b1,
    const float* __restrict__ W2, const float* __restrict__ b2) {
    extern __shared__ float smem[];
    float* sXT  = smem;                 // [64][LDT]  x^T tile
    float* sWT  = sXT  + 64 * LDT;      // [64][LDT]  sWT[j][i] = Weff[i][j]
    float* sW1  = sWT  + 64 * LDT;      // [64][LDT]  W1 row-major
    float* sW2T = sW1  + 64 * LDT;      // [64][LDT]  sW2T[k][i] = W2[i][k]
    float* sB1  = sW2T + 64 * LDT;      // [64]

    int n0 = blockIdx.x * 64;
    load_tile_T(x + (size_t)n0 * 64, sXT);
    load_tile_N(W1, sW1);
    load_tile_T(W2, sW2T);
    int t = threadIdx.x;
    if (t < 64) sB1[t] = b1[t];
    __syncthreads();

    int ty = t >> 4, tx = t & 15;

    // Weff[i][j] = sum_k W2[i][k] W1[k][j]; this thread: i = 4tx.., j = 4ty..
    u64 aw[4][2] = {};
#pragma unroll 16
    for (int k = 0; k < 64; k++) {
        float4 a = *reinterpret_cast<float4*>(&sW2T[k * LDT + 4 * tx]); // over i
        float4 b = *reinterpret_cast<float4*>(&sW1 [k * LDT + 4 * ty]); // over j
        u64 a01 = pk2(a.x, a.y), a23 = pk2(a.z, a.w);
        u64 d;
        d = dup2(b.x); fma2(aw[0][0], a01, d); fma2(aw[0][1], a23, d);
        d = dup2(b.y); fma2(aw[1][0], a01, d); fma2(aw[1][1], a23, d);
        d = dup2(b.z); fma2(aw[2][0], a01, d); fma2(aw[2][1], a23, d);
        d = dup2(b.w); fma2(aw[3][0], a01, d); fma2(aw[3][1], a23, d);
    }
    // b_eff for i = 4tx..4tx+3 (replicated across ty)
    float be[4];
    {
        float4 bv = *reinterpret_cast<const float4*>(&b2[4 * tx]);
        be[0] = bv.x; be[1] = bv.y; be[2] = bv.z; be[3] = bv.w;
#pragma unroll 16
        for (int k = 0; k < 64; k++) {
            float4 w = *reinterpret_cast<float4*>(&sW2T[k * LDT + 4 * tx]);
            float bk = sB1[k];
            be[0] = fmaf(w.x, bk, be[0]); be[1] = fmaf(w.y, bk, be[1]);
            be[2] = fmaf(w.z, bk, be[2]); be[3] = fmaf(w.w, bk, be[3]);
        }
    }
    // aw[jj] holds Weff[4tx+0..3][4ty+jj]  ->  sWT[j][i] = Weff[i][j]
#pragma unroll
    for (int jj = 0; jj < 4; jj++) {
        float2 lo = up2(aw[jj][0]), hi = up2(aw[jj][1]);
        float4 o = make_float4(lo.x, lo.y, hi.x, hi.y);
        *reinterpret_cast<float4*>(&sWT[(4 * ty + jj) * LDT + 4 * tx]) = o;
    }
    __syncthreads();

    // p = x @ Weff^T + b_eff
    u64 acc[4][2] = {};
#pragma unroll 16
    for (int j = 0; j < 64; j++) {
        float4 a = *reinterpret_cast<float4*>(&sXT[j * LDT + 4 * ty]);
        float4 b = *reinterpret_cast<float4*>(&sWT[j * LDT + 4 * tx]);
        u64 b01 = pk2(b.x, b.y), b23 = pk2(b.z, b.w);
        u64 d;
        d = dup2(a.x); fma2(acc[0][0], d, b01); fma2(acc[0][1], d, b23);
        d = dup2(a.y); fma2(acc[1][0], d, b01); fma2(acc[1][1], d, b23);
        d = dup2(a.z); fma2(acc[2][0], d, b01); fma2(acc[2][1], d, b23);
        d = dup2(a.w); fma2(acc[3][0], d, b01); fma2(acc[3][1], d, b23);
    }
#pragma unroll
    for (int r = 0; r < 4; r++) {
        float2 lo = up2(acc[r][0]), hi = up2(acc[r][1]);
        float4 o = make_float4(lo.x + be[0], lo.y + be[1],
                               hi.x + be[2], hi.y + be[3]);
        *reinterpret_cast<float4*>(
            &g_p[(size_t)(n0 + 4 * ty + r) * 64 + 4 * tx]) = o;
    }
}

// ----------------------------------------------------------------------------
// Kernel 2: flash attention + residual + projection + relu
// grid = (64, 4), 256 threads, 4x4 microtiles, FFMA2 inner loops
// ----------------------------------------------------------------------------
__global__ __launch_bounds__(256) void flash_kernel(
    const float* __restrict__ x, const float* __restrict__ W3,
    const float* __restrict__ b3, float* __restrict__ out) {
    extern __shared__ float smem[];
    float* sQT = smem;                  // [64][LDT]  Q^T
    float* sKT = sQT + 64 * LDT;        // [64][LDT]  K^T ; W3^T in epilogue
    float* sV  = sKT + 64 * LDT;        // [64][LDT]  V row-major
    float* sPT = sV  + 64 * LDT;        // [64][LDT]  P^T ; Z^T in epilogue

    int batch = blockIdx.y;
    int m0    = blockIdx.x * 64;
    const float* pb = g_p + (size_t)batch * NTOK * 64;
    const float* xb = x   + (size_t)batch * NTOK * 64;

    load_tile_T(pb + (size_t)m0 * 64, sQT);

    int t  = threadIdx.x;
    int ty = t >> 4, tx = t & 15;
    const float* qbase = sQT + 4 * ty;
    const float* kbase = sKT + 4 * tx;
    const float* pbase = sPT + 4 * ty;
    const float* vbase = sV  + 4 * tx;

    u64   Op[4][2] = {};                      // O accumulators, packed pairs
    float m[4] = {-1e30f, -1e30f, -1e30f, -1e30f};
    float l[4] = {};

    for (int j0 = 0; j0 < NTOK; j0 += 64) {
        __syncthreads();
        load_tile_T(pb + (size_t)j0 * 64, sKT);
        load_tile_N(xb + (size_t)j0 * 64, sV);
        __syncthreads();

        // --- GEMM1: S = Q K^T ---
        u64 Sp[4][2] = {};
#pragma unroll 16
        for (int k = 0; k < 64; k++) {
            float4 q  = *reinterpret_cast<const float4*>(qbase + k * LDT);
            float4 kk = *reinterpret_cast<const float4*>(kbase + k * LDT);
            u64 b01 = pk2(kk.x, kk.y), b23 = pk2(kk.z, kk.w);
            u64 d;
            d = dup2(q.x); fma2(Sp[0][0], d, b01); fma2(Sp[0][1], d, b23);
            d = dup2(q.y); fma2(Sp[1][0], d, b01); fma2(Sp[1][1], d, b23);
            d = dup2(q.z); fma2(Sp[2][0], d, b01); fma2(Sp[2][1], d, b23);
            d = dup2(q.w); fma2(Sp[3][0], d, b01); fma2(Sp[3][1], d, b23);
        }
        float S[4][4];
#pragma unroll
        for (int r = 0; r < 4; r++) {
            float2 lo = up2(Sp[r][0]), hi = up2(Sp[r][1]);
            S[r][0] = lo.x; S[r][1] = lo.y; S[r][2] = hi.x; S[r][3] = hi.y;
        }

        // --- online softmax (stats replicated across the 16 tx lanes) ---
#pragma unroll
        for (int r = 0; r < 4; r++) {
            float mx = fmaxf(fmaxf(S[r][0], S[r][1]), fmaxf(S[r][2], S[r][3]));
#pragma unroll
            for (int off = 8; off; off >>= 1)
                mx = fmaxf(mx, __shfl_xor_sync(0xffffffffu, mx, off));
            float mn   = fmaxf(m[r], mx);
            float corr = __expf(m[r] - mn);
            m[r] = mn;
            float rs = 0.f;
#pragma unroll
            for (int c = 0; c < 4; c++) { S[r][c] = __expf(S[r][c] - mn); rs += S[r][c]; }
#pragma unroll
            for (int off = 8; off; off >>= 1)
                rs += __shfl_xor_sync(0xffffffffu, rs, off);
            l[r] = l[r] * corr + rs;
            u64 c2 = dup2(corr);
            mul2(Op[r][0], c2); mul2(Op[r][1], c2);
        }

        // --- store P transposed: sPT[key][row] ---
#pragma unroll
        for (int c = 0; c < 4; c++) {
            float4 pv = make_float4(S[0][c], S[1][c], S[2][c], S[3][c]);
            *reinterpret_cast<float4*>(&sPT[(4 * tx + c) * LDT + 4 * ty]) = pv;
        }
        __syncthreads();

        // --- GEMM2: O += P V ---
#pragma unroll 16
        for (int j = 0; j < 64; j++) {
            float4 pp = *reinterpret_cast<const float4*>(pbase + j * LDT);
            float4 vv = *reinterpret_cast<const float4*>(vbase + j * LDT);
            u64 b01 = pk2(vv.x, vv.y), b23 = pk2(vv.z, vv.w);
            u64 d;
            d = dup2(pp.x); fma2(Op[0][0], d, b01); fma2(Op[0][1], d, b23);
            d = dup2(pp.y); fma2(Op[1][0], d, b01); fma2(Op[1][1], d, b23);
            d = dup2(pp.z); fma2(Op[2][0], d, b01); fma2(Op[2][1], d, b23);
            d = dup2(pp.w); fma2(Op[3][0], d, b01); fma2(Op[3][1], d, b23);
        }
    }

    // ========================= epilogue =========================
    __syncthreads();
    load_tile_T(W3, sKT);   // sKT[f][o] = W3[o][f]

    // z = 0.5*(O/l + x_row), stored transposed into sPT
    float z[4][4];
#pragma unroll
    for (int r = 0; r < 4; r++) {
        float inv = 0.5f / l[r];
        float4 xv = *reinterpret_cast<const float4*>(
            &xb[(size_t)(m0 + 4 * ty + r) * 64 + 4 * tx]);
        float2 lo = up2(Op[r][0]), hi = up2(Op[r][1]);
        z[r][0] = lo.x * inv + 0.5f * xv.x;
        z[r][1] = lo.y * inv + 0.5f * xv.y;
        z[r][2] = hi.x * inv + 0.5f * xv.z;
        z[r][3] = hi.y * inv + 0.5f * xv.w;
    }
#pragma unroll
    for (int f = 0; f < 4; f++) {
        float4 zv = make_float4(z[0][f], z[1][f], z[2][f], z[3][f]);
        *reinterpret_cast<float4*>(&sPT[(4 * tx + f) * LDT + 4 * ty]) = zv;
    }
    __syncthreads();

    // out = relu(Z @ W3^T + b3)
    u64 acc[4][2] = {};
#pragma unroll 16
    for (int f = 0; f < 64; f++) {
        float4 zz = *reinterpret_cast<const float4*>(pbase + f * LDT);
        float4 ww = *reinterpret_cast<const float4*>(kbase + f * LDT);
        u64 b01 = pk2(ww.x, ww.y), b23 = pk2(ww.z, ww.w);
        u64 d;
        d = dup2(zz.x); fma2(acc[0][0], d, b01); fma2(acc[0][1], d, b23);
        d = dup2(zz.y); fma2(acc[1][0], d, b01); fma2(acc[1][1], d, b23);
        d = dup2(zz.z); fma2(acc[2][0], d, b01); fma2(acc[2][1], d, b23);
        d = dup2(zz.w); fma2(acc[3][0], d, b01); fma2(acc[3][1], d, b23);
    }
    float4 bbv = *reinterpret_cast<const float4*>(&b3[4 * tx]);
#pragma unroll
    for (int r = 0; r < 4; r++) {
        float2 lo = up2(acc[r][0]), hi = up2(acc[r][1]);
        float4 res = make_float4(fmaxf(lo.x + bbv.x, 0.f),
                                 fmaxf(lo.y + bbv.y, 0.f),
                                 fmaxf(hi.x + bbv.z, 0.f),
                                 fmaxf(hi.y + bbv.w, 0.f));
        *reinterpret_cast<float4*>(
            &out[((size_t)batch * NTOK + m0 + 4 * ty + r) * 64 + 4 * tx]) = res;
    }
}

// ----------------------------------------------------------------------------
extern "C" void kernel_launch(void* const* d_in, const int* in_sizes, int n_in,
                              void* d_out, int out_size) {
    (void)in_sizes; (void)n_in; (void)out_size;
    const float* x  = (const float*)d_in[0];
    const float* W1 = (const float*)d_in[1];
    const float* b1 = (const float*)d_in[2];
    const float* W2 = (const float*)d_in[3];
    const float* b2 = (const float*)d_in[4];
    const float* W3 = (const float*)d_in[5];
    const float* b3 = (const float*)d_in[6];
    float* out = (float*)d_out;

    constexpr int P_SMEM     = (4 * 64 * LDT + 64) * (int)sizeof(float); // 69888
    constexpr int FLASH_SMEM = 4 * 64 * LDT * (int)sizeof(float);        // 69632
    static bool attr_done = false;
    if (!attr_done) {
        cudaFuncSetAttribute(p_kernel,
                             cudaFuncAttributeMaxDynamicSharedMemorySize, P_SMEM);
        cudaFuncSetAttribute(flash_kernel,
                             cudaFuncAttributeMaxDynamicSharedMemorySize, FLASH_SMEM);
        attr_done = true;
    }

    p_kernel<<<BATCH * NTOK / 64, 256, P_SMEM>>>(x, W1, b1, W2, b2);
    flash_kernel<<<dim3(NTOK / 64, BATCH), 256, FLASH_SMEM>>>(x, W3, b3, out);
}

// round 11
// speedup vs baseline: 2.7885x; 2.7885x over previous
#include <cuda_runtime.h>
#include <cuda_bf16.h>

using u32 = unsigned; using u64 = unsigned long long;

#define LDT 68
static constexpr int BATCH = 4, NTOK = 4096, MT = 64, KT = 128, NSTEP = NTOK / KT;

// single extern-shared symbol for the whole TU
extern __shared__ char hx_smem[];

// ---- device scratch (alloc-free) -------------------------------------------
__device__ u32   gKH[16384 * 32];        // p hi, bf16x2 [row][32]
__device__ u32   gKL[16384 * 32];        // p lo
__device__ u32   gVH[BATCH * 64 * 2048]; // x^T hi, bf16x2 [b][f][2048 keypairs]
__device__ u32   gVL[BATCH * 64 * 2048];
__device__ float g_m[BATCH * NTOK];      // softmax shift = |p_row|^2

// ---- helpers -----------------------------------------------------------------
__device__ __forceinline__ u32 cvt2bf(float lo, float hi) {   // low half = lo
    u32 r; asm("cvt.rn.bf16x2.f32 %0, %1, %2;" : "=r"(r) : "f"(hi), "f"(lo)); return r;
}
__device__ __forceinline__ float bflo(u32 u) { return __uint_as_float(u << 16); }
__device__ __forceinline__ float bfhi(u32 u) { return __uint_as_float(u & 0xffff0000u); }

__device__ __forceinline__ void mma16816(float* d, const u32* a, const u32* b) {
    asm volatile(
        "mma.sync.aligned.m16n8k16.row.col.f32.bf16.bf16.f32 "
        "{%0,%1,%2,%3}, {%4,%5,%6,%7}, {%8,%9}, {%0,%1,%2,%3};"
        : "+f"(d[0]), "+f"(d[1]), "+f"(d[2]), "+f"(d[3])
        : "r"(a[0]), "r"(a[1]), "r"(a[2]), "r"(a[3]), "r"(b[0]), "r"(b[1]));
}

// fp32 packed helpers (p_kernel)
__device__ __forceinline__ u64 pk2(float x, float y) {
    u64 r; asm("mov.b64 %0, {%1, %2};" : "=l"(r) : "f"(x), "f"(y)); return r;
}
__device__ __forceinline__ u64 dup2(float x) {
    u64 r; asm("mov.b64 %0, {%1, %1};" : "=l"(r) : "f"(x)); return r;
}
__device__ __forceinline__ void fma2(u64& d, u64 a, u64 b) {
    asm("fma.rn.f32x2 %0, %1, %2, %0;" : "+l"(d) : "l"(a), "l"(b));
}
__device__ __forceinline__ float2 up2(u64 v) {
    float2 f; asm("mov.b64 {%0, %1}, %2;" : "=f"(f.x), "=f"(f.y) : "l"(v)); return f;
}

// ---- fp32 64x64 tile loaders ---------------------------------------------------
__device__ __forceinline__ void load_tile_T(const float* __restrict__ g, float* s) {
    int t = threadIdx.x;
#pragma unroll
    for (int i = 0; i < 4; i++) {
        int idx = t + i * 256, n = idx >> 4, k4 = (idx & 15) << 2;
        float4 v = *reinterpret_cast<const float4*>(g + n * 64 + k4);
        s[(k4+0)*LDT+n] = v.x; s[(k4+1)*LDT+n] = v.y;
        s[(k4+2)*LDT+n] = v.z; s[(k4+3)*LDT+n] = v.w;
    }
}
__device__ __forceinline__ void load_tile_N(const float* __restrict__ g, float* s) {
    int t = threadIdx.x;
#pragma unroll
    for (int i = 0; i < 4; i++) {
        int idx = t + i * 256, n = idx >> 4, k4 = (idx & 15) << 2;
        *reinterpret_cast<float4*>(s + n * LDT + k4) =
            *reinterpret_cast<const float4*>(g + n * 64 + k4);
    }
}

// ============================================================================
// Kernel 1: Weff/beff + p = x@Weff^T + beff; emit p hi/lo (gK*), x^T hi/lo
// (gV*), g_m = |p_row|^2.  grid 256, block 256.  (unchanged from R9 — compiled)
// ============================================================================
__global__ __launch_bounds__(256) void p_kernel(
    const float* __restrict__ x,
    const float* __restrict__ W1, const float* __restrict__ b1,
    const float* __restrict__ W2, const float* __restrict__ b2) {
    float* smem = reinterpret_cast<float*>(hx_smem);
    float* sXT  = smem;
    float* sWT  = sXT  + 64 * LDT;
    float* sW1  = sWT  + 64 * LDT;
    float* sW2T = sW1  + 64 * LDT;
    float* sB1  = sW2T + 64 * LDT;

    int n0 = blockIdx.x * 64;
    load_tile_T(x + (size_t)n0 * 64, sXT);
    load_tile_N(W1, sW1);
    load_tile_T(W2, sW2T);
    int t = threadIdx.x;
    if (t < 64) sB1[t] = b1[t];
    __syncthreads();

    int ty = t >> 4, tx = t & 15;

    u64 aw[4][2] = {};
#pragma unroll 16
    for (int k = 0; k < 64; k++) {
        float4 a = *reinterpret_cast<float4*>(&sW2T[k * LDT + 4 * tx]);
        float4 b = *reinterpret_cast<float4*>(&sW1 [k * LDT + 4 * ty]);
        u64 a01 = pk2(a.x, a.y), a23 = pk2(a.z, a.w), d;
        d = dup2(b.x); fma2(aw[0][0], a01, d); fma2(aw[0][1], a23, d);
        d = dup2(b.y); fma2(aw[1][0], a01, d); fma2(aw[1][1], a23, d);
        d = dup2(b.z); fma2(aw[2][0], a01, d); fma2(aw[2][1], a23, d);
        d = dup2(b.w); fma2(aw[3][0], a01, d); fma2(aw[3][1], a23, d);
    }
    float be[4];
    {
        float4 bv = *reinterpret_cast<const float4*>(&b2[4 * tx]);
        be[0]=bv.x; be[1]=bv.y; be[2]=bv.z; be[3]=bv.w;
#pragma unroll 16
        for (int k = 0; k < 64; k++) {
            float4 w = *reinterpret_cast<float4*>(&sW2T[k * LDT + 4 * tx]);
            float bk = sB1[k];
            be[0]=fmaf(w.x,bk,be[0]); be[1]=fmaf(w.y,bk,be[1]);
            be[2]=fmaf(w.z,bk,be[2]); be[3]=fmaf(w.w,bk,be[3]);
        }
    }
#pragma unroll
    for (int jj = 0; jj < 4; jj++) {
        float2 lo = up2(aw[jj][0]), hi = up2(aw[jj][1]);
        *reinterpret_cast<float4*>(&sWT[(4*ty+jj)*LDT + 4*tx]) =
            make_float4(lo.x, lo.y, hi.x, hi.y);
    }
    __syncthreads();

    u64 acc[4][2] = {};
#pragma unroll 16
    for (int j = 0; j < 64; j++) {
        float4 a = *reinterpret_cast<float4*>(&sXT[j * LDT + 4 * ty]);
        float4 b = *reinterpret_cast<float4*>(&sWT[j * LDT + 4 * tx]);
        u64 b01 = pk2(b.x, b.y), b23 = pk2(b.z, b.w), d;
        d = dup2(a.x); fma2(acc[0][0], d, b01); fma2(acc[0][1], d, b23);
        d = dup2(a.y); fma2(acc[1][0], d, b01); fma2(acc[1][1], d, b23);
        d = dup2(a.z); fma2(acc[2][0], d, b01); fma2(acc[2][1], d, b23);
        d = dup2(a.w); fma2(acc[3][0], d, b01); fma2(acc[3][1], d, b23);
    }
#pragma unroll
    for (int r = 0; r < 4; r++) {
        float2 lo = up2(acc[r][0]), hi = up2(acc[r][1]);
        float p0 = lo.x+be[0], p1 = lo.y+be[1], p2 = hi.x+be[2], p3 = hi.y+be[3];
        int row = n0 + 4 * ty + r;
        u32 h01 = cvt2bf(p0, p1), h23 = cvt2bf(p2, p3);
        u32 l01 = cvt2bf(p0 - bflo(h01), p1 - bfhi(h01));
        u32 l23 = cvt2bf(p2 - bflo(h23), p3 - bfhi(h23));
        *reinterpret_cast<uint2*>(&gKH[(size_t)row * 32 + 2 * tx]) = make_uint2(h01, h23);
        *reinterpret_cast<uint2*>(&gKL[(size_t)row * 32 + 2 * tx]) = make_uint2(l01, l23);
        float msq = p0*p0 + p1*p1 + p2*p2 + p3*p3;
#pragma unroll
        for (int off = 8; off; off >>= 1)
            msq += __shfl_xor_sync(0xffffffffu, msq, off);
        if (tx == 0) g_m[row] = msq;
    }

    // x^T hi/lo -> gV*
    {
        int b  = n0 >> 12, kb = n0 & 4095;
        int f  = t >> 2, q = t & 3;
        const float* src = &sXT[f * LDT + 16 * q];
        u32 h[8], l[8];
#pragma unroll
        for (int i = 0; i < 8; i++) {
            float v0 = src[2*i], v1 = src[2*i+1];
            h[i] = cvt2bf(v0, v1);
            l[i] = cvt2bf(v0 - bflo(h[i]), v1 - bfhi(h[i]));
        }
        size_t base = ((size_t)b * 64 + f) * 2048 + (kb >> 1) + 8 * q;
        *reinterpret_cast<uint4*>(&gVH[base    ]) = make_uint4(h[0],h[1],h[2],h[3]);
        *reinterpret_cast<uint4*>(&gVH[base + 4]) = make_uint4(h[4],h[5],h[6],h[7]);
        *reinterpret_cast<uint4*>(&gVL[base    ]) = make_uint4(l[0],l[1],l[2],l[3]);
        *reinterpret_cast<uint4*>(&gVL[base + 4]) = make_uint4(l[4],l[5],l[6],l[7]);
    }
}

// ============================================================================
// Kernel 2: mma.sync bf16 flash. grid (64, 4), 256 threads = 8 warps.
// Warp w: q rows 16*(w/2)..+15, keys 64*(w&1)..+63 of each 128-key step.
// ============================================================================
__global__ __launch_bounds__(256, 2) void flash_mma(
    const float* __restrict__ x, const float* __restrict__ W3,
    const float* __restrict__ b3, float* __restrict__ out) {
    u32* sm  = reinterpret_cast<u32*>(hx_smem);
    u32* sKh = sm;             // [128 keys][32 u32], swizzled
    u32* sKl = sm + 4096;
    u32* sVh = sm + 8192;      // [64 f][64 keypairs], swizzled
    u32* sVl = sm + 12288;

    int t = threadIdx.x, w = t >> 5, lane = t & 31;
    int gid = lane >> 2, tig = lane & 3;
    int r0  = (w >> 1) * 16;       // row group base (0..48)
    int ko  = (w & 1) * 64;        // key half offset
    int batch = blockIdx.y, m0 = blockIdx.x * MT;
    size_t rowbase = (size_t)batch * NTOK;

    // ---- persistent Q fragments (hi/lo), 4 k-chunks ----
    u32 qh[4][4], ql[4][4];
    {
        size_t ra = (rowbase + m0 + r0 + gid) * 32;
        size_t rb = ra + 8 * 32;
#pragma unroll
        for (int c = 0; c < 4; c++) {
            qh[c][0] = gKH[ra + 8*c + tig];     qh[c][1] = gKH[rb + 8*c + tig];
            qh[c][2] = gKH[ra + 8*c + 4 + tig]; qh[c][3] = gKH[rb + 8*c + 4 + tig];
            ql[c][0] = gKL[ra + 8*c + tig];     ql[c][1] = gKL[rb + 8*c + tig];
            ql[c][2] = gKL[ra + 8*c + 4 + tig]; ql[c][3] = gKL[rb + 8*c + 4 + tig];
        }
    }
    float m0r = g_m[rowbase + m0 + r0 + gid];
    float m1r = g_m[rowbase + m0 + r0 + gid + 8];
    float l0 = 0.f, l1 = 0.f;
    float O[8][4] = {};

    const u32* vh = gVH + (size_t)batch * 64 * 2048;
    const u32* vl = gVL + (size_t)batch * 64 * 2048;

    for (int step = 0; step < NSTEP; step++) {
        int j0 = step * KT;
        __syncthreads();
        // load K tiles (hi/lo), swizzle (c4 + 4*key)&31
#pragma unroll
        for (int i = 0; i < 4; i++) {
            int idx = t + 256 * i;
            int key = idx >> 3, c4 = (idx & 7) << 2;
            u32 pos = (u32)key * 32 + (u32)((c4 + 4 * key) & 31);
            *reinterpret_cast<uint4*>(&sKh[pos]) =
                *reinterpret_cast<const uint4*>(&gKH[(rowbase + j0 + key) * 32 + c4]);
            *reinterpret_cast<uint4*>(&sKl[pos]) =
                *reinterpret_cast<const uint4*>(&gKL[(rowbase + j0 + key) * 32 + c4]);
        }
        // load V^T tiles (hi/lo), swizzle (c4 + 4*f)&63
#pragma unroll
        for (int i = 0; i < 4; i++) {
            int idx = t + 256 * i;
            int f = idx >> 4, c4 = (idx & 15) << 2;
            u32 pos = (u32)f * 64 + (u32)((c4 + 4 * f) & 63);
            *reinterpret_cast<uint4*>(&sVh[pos]) =
                *reinterpret_cast<const uint4*>(&vh[(size_t)f * 2048 + (j0 >> 1) + c4]);
            *reinterpret_cast<uint4*>(&sVl[pos]) =
                *reinterpret_cast<const uint4*>(&vl[(size_t)f * 2048 + (j0 >> 1) + c4]);
        }
        __syncthreads();

        // ---- GEMM1: S = QhKh + QhKl + QlKh ----
        float S[8][4] = {};
#pragma unroll
        for (int c = 0; c < 4; c++) {
#pragma unroll
            for (int nn = 0; nn < 8; nn++) {
                int key = ko + 8 * nn + gid;
                u32 base = (u32)key * 32;
                u32 p0 = base + (u32)((8*c     + tig + 4*key) & 31);
                u32 p1 = base + (u32)((8*c + 4 + tig + 4*key) & 31);
                u32 bh[2] = { sKh[p0], sKh[p1] };
                u32 bl[2] = { sKl[p0], sKl[p1] };
                mma16816(S[nn], qh[c], bh);
                mma16816(S[nn], qh[c], bl);
                mma16816(S[nn], ql[c], bh);
            }
        }
        // ---- softmax (fixed shift) ----
#pragma unroll
        for (int nn = 0; nn < 8; nn++) {
            float e0 = __expf(S[nn][0] - m0r), e1 = __expf(S[nn][1] - m0r);
            float e2 = __expf(S[nn][2] - m1r), e3 = __expf(S[nn][3] - m1r);
            l0 += e0 + e1; l1 += e2 + e3;
            S[nn][0] = e0; S[nn][1] = e1; S[nn][2] = e2; S[nn][3] = e3;
        }
        // ---- GEMM2: O += PhVh + PhVl + PlVh ----
#pragma unroll
        for (int c = 0; c < 4; c++) {
            // P a-frags straight from S c-frags (chunks 2c, 2c+1)
            u32 ph[4], pl[4];
            {
                float a, b;
                a = S[2*c][0];   b = S[2*c][1];
                ph[0] = cvt2bf(a, b); pl[0] = cvt2bf(a - bflo(ph[0]), b - bfhi(ph[0]));
                a = S[2*c][2];   b = S[2*c][3];
                ph[1] = cvt2bf(a, b); pl[1] = cvt2bf(a - bflo(ph[1]), b - bfhi(ph[1]));
                a = S[2*c+1][0]; b = S[2*c+1][1];
                ph[2] = cvt2bf(a, b); pl[2] = cvt2bf(a - bflo(ph[2]), b - bfhi(ph[2]));
                a = S[2*c+1][2]; b = S[2*c+1][3];
                ph[3] = cvt2bf(a, b); pl[3] = cvt2bf(a - bflo(ph[3]), b - bfhi(ph[3]));
            }
#pragma unroll
            for (int nn = 0; nn < 8; nn++) {
                int f = 8 * nn + gid;
                u32 base = (u32)f * 64;
                u32 j = (u32)(ko >> 1) + 8 * c + tig;
                u32 p0 = base + ((j     + 4 * (u32)f) & 63);
                u32 p1 = base + ((j + 4 + 4 * (u32)f) & 63);
                u32 bh[2] = { sVh[p0], sVh[p1] };
                u32 bl[2] = { sVl[p0], sVl[p1] };
                mma16816(O[nn], ph, bh);
                mma16816(O[nn], ph, bl);
                mma16816(O[nn], pl, bh);
            }
        }
    }

    // ===================== combine halves + epilogue =====================
    l0 += __shfl_xor_sync(0xffffffffu, l0, 1);
    l0 += __shfl_xor_sync(0xffffffffu, l0, 2);
    l1 += __shfl_xor_sync(0xffffffffu, l1, 1);
    l1 += __shfl_xor_sync(0xffffffffu, l1, 2);

    __syncthreads();                         // all GEMMs done; tiles dead
    float* sO  = reinterpret_cast<float*>(hx_smem);   // [2][64][68]
    float* sLp = sO + 2 * 64 * 68;                    // [2][64]
    float* zT  = sLp + 128;                           // [64 f][68]
    float* wT  = zT + 64 * 68;                        // [64 f][68]

#pragma unroll
    for (int nn = 0; nn < 8; nn++) {
        int f = 8 * nn + 2 * tig;
        int rA = (w & 1) * 64 + r0 + gid;
        sO[rA * 68 + f]       = O[nn][0];
        sO[rA * 68 + f + 1]   = O[nn][1];
        sO[(rA+8) * 68 + f]   = O[nn][2];
        sO[(rA+8) * 68 + f+1] = O[nn][3];
    }
    if (tig == 0) {
        sLp[(w & 1) * 64 + r0 + gid]     = l0;
        sLp[(w & 1) * 64 + r0 + gid + 8] = l1;
    }
    __syncthreads();

    // z = 0.5*(O/l + x), stored transposed zT[f][row]
#pragma unroll
    for (int i = 0; i < 4; i++) {
        int idx = t + 256 * i;
        int row = idx >> 4, f4 = (idx & 15) << 2;
        float l   = sLp[row] + sLp[64 + row];
        float inv = 0.5f / l;
        float4 xv = *reinterpret_cast<const float4*>(&x[(rowbase + m0 + row) * 64 + f4]);
        float4 o0 = *reinterpret_cast<float4*>(&sO[row * 68 + f4]);
        float4 o1 = *reinterpret_cast<float4*>(&sO[(64 + row) * 68 + f4]);
        zT[(f4+0) * 68 + row] = (o0.x + o1.x) * inv + 0.5f * xv.x;
        zT[(f4+1) * 68 + row] = (o0.y + o1.y) * inv + 0.5f * xv.y;
        zT[(f4+2) * 68 + row] = (o0.z + o1.z) * inv + 0.5f * xv.z;
        zT[(f4+3) * 68 + row] = (o0.w + o1.w) * inv + 0.5f * xv.w;
    }
    load_tile_T(W3, wT);
    __syncthreads();

    // out = relu(Z @ W3^T + b3), SIMT 4x4 microtile over 64x64
    int ty = t >> 4, tx = t & 15;
    float acc[4][4] = {};
#pragma unroll 8
    for (int f = 0; f < 64; f++) {
        float4 zz = *reinterpret_cast<float4*>(&zT[f * 68 + 4 * ty]);
        float4 ww = *reinterpret_cast<float4*>(&wT[f * 68 + 4 * tx]);
        float zr[4] = {zz.x, zz.y, zz.z, zz.w};
        float wo[4] = {ww.x, ww.y, ww.z, ww.w};
#pragma unroll
        for (int r = 0; r < 4; r++)
#pragma unroll
            for (int o = 0; o < 4; o++) acc[r][o] = fmaf(zr[r], wo[o], acc[r][o]);
    }
    float4 bbv = *reinterpret_cast<const float4*>(&b3[4 * tx]);
#pragma unroll
    for (int r = 0; r < 4; r++) {
        float4 res = make_float4(fmaxf(acc[r][0] + bbv.x, 0.f),
                                 fmaxf(acc[r][1] + bbv.y, 0.f),
                                 fmaxf(acc[r][2] + bbv.z, 0.f),
                                 fmaxf(acc[r][3] + bbv.w, 0.f));
        *reinterpret_cast<float4*>(
            &out[(rowbase + m0 + 4 * ty + r) * 64 + 4 * tx]) = res;
    }
}

// ----------------------------------------------------------------------------
extern "C" void kernel_launch(void* const* d_in, const int* in_sizes, int n_in,
                              void* d_out, int out_size) {
    (void)in_sizes; (void)n_in; (void)out_size;
    const float* x  = (const float*)d_in[0];
    const float* W1 = (const float*)d_in[1];
    const float* b1 = (const float*)d_in[2];
    const float* W2 = (const float*)d_in[3];
    const float* b2 = (const float*)d_in[4];
    const float* W3 = (const float*)d_in[5];
    const float* b3 = (const float*)d_in[6];
    float* out = (float*)d_out;

    constexpr int P_SMEM     = (4 * 64 * LDT + 64) * (int)sizeof(float);
    constexpr int FLASH_SMEM = (2*64*68 + 128 + 2*64*68) * (int)sizeof(float); // 70144
    static bool done = false;
    if (!done) {
        cudaFuncSetAttribute(p_kernel,
            cudaFuncAttributeMaxDynamicSharedMemorySize, P_SMEM);
        cudaFuncSetAttribute(flash_mma,
            cudaFuncAttributeMaxDynamicSharedMemorySize, FLASH_SMEM);
        done = true;
    }
    p_kernel<<<BATCH * NTOK / 64, 256, P_SMEM>>>(x, W1, b1, W2, b2);
    flash_mma<<<dim3(NTOK / MT, BATCH), 256, FLASH_SMEM>>>(x, W3, b3, out);
}

// round 12
// speedup vs baseline: 3.0180x; 1.0823x over previous
#include <cuda_runtime.h>
#include <cuda_bf16.h>

using u32 = unsigned; using u64 = unsigned long long;

#define LDT 68
static constexpr int BATCH = 4, NTOK = 4096, MT = 64, KT = 64, NSTEP = NTOK / KT;

// single extern-shared symbol for the whole TU
extern __shared__ char hx_smem[];

// ---- device scratch (alloc-free) -------------------------------------------
__device__ u32   gKH[16384 * 32];        // p hi, bf16x2 [row][32]
__device__ u32   gKL[16384 * 32];        // p lo
__device__ u32   gVH[BATCH * 64 * 2048]; // x^T hi, bf16x2 [b][f][2048 keypairs]
__device__ u32   gVL[BATCH * 64 * 2048];
__device__ float g_m[BATCH * NTOK];      // softmax shift = |p_row|^2

// ---- helpers -----------------------------------------------------------------
__device__ __forceinline__ u32 smem_u32(const void* p) {
    u32 a; asm("{ .reg .u64 t; cvta.to.shared.u64 t, %1; cvt.u32.u64 %0, t; }"
               : "=r"(a) : "l"(p)); return a;
}
__device__ __forceinline__ u32 cvt2bf(float lo, float hi) {   // low half = lo
    u32 r; asm("cvt.rn.bf16x2.f32 %0, %1, %2;" : "=r"(r) : "f"(hi), "f"(lo)); return r;
}
__device__ __forceinline__ float bflo(u32 u) { return __uint_as_float(u << 16); }
__device__ __forceinline__ float bfhi(u32 u) { return __uint_as_float(u & 0xffff0000u); }

__device__ __forceinline__ void mma16816(float* d, const u32* a, const u32* b) {
    asm volatile(
        "mma.sync.aligned.m16n8k16.row.col.f32.bf16.bf16.f32 "
        "{%0,%1,%2,%3}, {%4,%5,%6,%7}, {%8,%9}, {%0,%1,%2,%3};"
        : "+f"(d[0]), "+f"(d[1]), "+f"(d[2]), "+f"(d[3])
        : "r"(a[0]), "r"(a[1]), "r"(a[2]), "r"(a[3]), "r"(b[0]), "r"(b[1]));
}

__device__ __forceinline__ void cp16(u32 dst, const void* src) {
    asm volatile("cp.async.cg.shared.global [%0], [%1], 16;"
                 :: "r"(dst), "l"(src) : "memory");
}
#define CP_COMMIT() asm volatile("cp.async.commit_group;" ::: "memory")
#define CP_WAIT(n)  asm volatile("cp.async.wait_group %0;" :: "n"(n) : "memory")

// fp32 packed helpers (p_kernel)
__device__ __forceinline__ u64 pk2(float x, float y) {
    u64 r; asm("mov.b64 %0, {%1, %2};" : "=l"(r) : "f"(x), "f"(y)); return r;
}
__device__ __forceinline__ u64 dup2(float x) {
    u64 r; asm("mov.b64 %0, {%1, %1};" : "=l"(r) : "f"(x)); return r;
}
__device__ __forceinline__ void fma2(u64& d, u64 a, u64 b) {
    asm("fma.rn.f32x2 %0, %1, %2, %0;" : "+l"(d) : "l"(a), "l"(b));
}
__device__ __forceinline__ float2 up2(u64 v) {
    float2 f; asm("mov.b64 {%0, %1}, %2;" : "=f"(f.x), "=f"(f.y) : "l"(v)); return f;
}

// ---- fp32 64x64 tile loaders ---------------------------------------------------
__device__ __forceinline__ void load_tile_T(const float* __restrict__ g, float* s) {
    int t = threadIdx.x;
#pragma unroll
    for (int i = 0; i < 4; i++) {
        int idx = t + i * 256, n = idx >> 4, k4 = (idx & 15) << 2;
        float4 v = *reinterpret_cast<const float4*>(g + n * 64 + k4);
        s[(k4+0)*LDT+n] = v.x; s[(k4+1)*LDT+n] = v.y;
        s[(k4+2)*LDT+n] = v.z; s[(k4+3)*LDT+n] = v.w;
    }
}
__device__ __forceinline__ void load_tile_N(const float* __restrict__ g, float* s) {
    int t = threadIdx.x;
#pragma unroll
    for (int i = 0; i < 4; i++) {
        int idx = t + i * 256, n = idx >> 4, k4 = (idx & 15) << 2;
        *reinterpret_cast<float4*>(s + n * LDT + k4) =
            *reinterpret_cast<const float4*>(g + n * 64 + k4);
    }
}

// ============================================================================
// Kernel 1: Weff/beff + p = x@Weff^T + beff; emit p hi/lo (gK*), x^T hi/lo
// (gV*), g_m = |p_row|^2.  grid 256, block 256.  (unchanged — proven)
// ============================================================================
__global__ __launch_bounds__(256) void p_kernel(
    const float* __restrict__ x,
    const float* __restrict__ W1, const float* __restrict__ b1,
    const float* __restrict__ W2, const float* __restrict__ b2) {
    float* smem = reinterpret_cast<float*>(hx_smem);
    float* sXT  = smem;
    float* sWT  = sXT  + 64 * LDT;
    float* sW1  = sWT  + 64 * LDT;
    float* sW2T = sW1  + 64 * LDT;
    float* sB1  = sW2T + 64 * LDT;

    int n0 = blockIdx.x * 64;
    load_tile_T(x + (size_t)n0 * 64, sXT);
    load_tile_N(W1, sW1);
    load_tile_T(W2, sW2T);
    int t = threadIdx.x;
    if (t < 64) sB1[t] = b1[t];
    __syncthreads();

    int ty = t >> 4, tx = t & 15;

    u64 aw[4][2] = {};
#pragma unroll 16
    for (int k = 0; k < 64; k++) {
        float4 a = *reinterpret_cast<float4*>(&sW2T[k * LDT + 4 * tx]);
        float4 b = *reinterpret_cast<float4*>(&sW1 [k * LDT + 4 * ty]);
        u64 a01 = pk2(a.x, a.y), a23 = pk2(a.z, a.w), d;
        d = dup2(b.x); fma2(aw[0][0], a01, d); fma2(aw[0][1], a23, d);
        d = dup2(b.y); fma2(aw[1][0], a01, d); fma2(aw[1][1], a23, d);
        d = dup2(b.z); fma2(aw[2][0], a01, d); fma2(aw[2][1], a23, d);
        d = dup2(b.w); fma2(aw[3][0], a01, d); fma2(aw[3][1], a23, d);
    }
    float be[4];
    {
        float4 bv = *reinterpret_cast<const float4*>(&b2[4 * tx]);
        be[0]=bv.x; be[1]=bv.y; be[2]=bv.z; be[3]=bv.w;
#pragma unroll 16
        for (int k = 0; k < 64; k++) {
            float4 w = *reinterpret_cast<float4*>(&sW2T[k * LDT + 4 * tx]);
            float bk = sB1[k];
            be[0]=fmaf(w.x,bk,be[0]); be[1]=fmaf(w.y,bk,be[1]);
            be[2]=fmaf(w.z,bk,be[2]); be[3]=fmaf(w.w,bk,be[3]);
        }
    }
#pragma unroll
    for (int jj = 0; jj < 4; jj++) {
        float2 lo = up2(aw[jj][0]), hi = up2(aw[jj][1]);
        *reinterpret_cast<float4*>(&sWT[(4*ty+jj)*LDT + 4*tx]) =
            make_float4(lo.x, lo.y, hi.x, hi.y);
    }
    __syncthreads();

    u64 acc[4][2] = {};
#pragma unroll 16
    for (int j = 0; j < 64; j++) {
        float4 a = *reinterpret_cast<float4*>(&sXT[j * LDT + 4 * ty]);
        float4 b = *reinterpret_cast<float4*>(&sWT[j * LDT + 4 * tx]);
        u64 b01 = pk2(b.x, b.y), b23 = pk2(b.z, b.w), d;
        d = dup2(a.x); fma2(acc[0][0], d, b01); fma2(acc[0][1], d, b23);
        d = dup2(a.y); fma2(acc[1][0], d, b01); fma2(acc[1][1], d, b23);
        d = dup2(a.z); fma2(acc[2][0], d, b01); fma2(acc[2][1], d, b23);
        d = dup2(a.w); fma2(acc[3][0], d, b01); fma2(acc[3][1], d, b23);
    }
#pragma unroll
    for (int r = 0; r < 4; r++) {
        float2 lo = up2(acc[r][0]), hi = up2(acc[r][1]);
        float p0 = lo.x+be[0], p1 = lo.y+be[1], p2 = hi.x+be[2], p3 = hi.y+be[3];
        int row = n0 + 4 * ty + r;
        u32 h01 = cvt2bf(p0, p1), h23 = cvt2bf(p2, p3);
        u32 l01 = cvt2bf(p0 - bflo(h01), p1 - bfhi(h01));
        u32 l23 = cvt2bf(p2 - bflo(h23), p3 - bfhi(h23));
        *reinterpret_cast<uint2*>(&gKH[(size_t)row * 32 + 2 * tx]) = make_uint2(h01, h23);
        *reinterpret_cast<uint2*>(&gKL[(size_t)row * 32 + 2 * tx]) = make_uint2(l01, l23);
        float msq = p0*p0 + p1*p1 + p2*p2 + p3*p3;
#pragma unroll
        for (int off = 8; off; off >>= 1)
            msq += __shfl_xor_sync(0xffffffffu, msq, off);
        if (tx == 0) g_m[row] = msq;
    }

    // x^T hi/lo -> gV*
    {
        int b  = n0 >> 12, kb = n0 & 4095;
        int f  = t >> 2, q = t & 3;
        const float* src = &sXT[f * LDT + 16 * q];
        u32 h[8], l[8];
#pragma unroll
        for (int i = 0; i < 8; i++) {
            float v0 = src[2*i], v1 = src[2*i+1];
            h[i] = cvt2bf(v0, v1);
            l[i] = cvt2bf(v0 - bflo(h[i]), v1 - bfhi(h[i]));
        }
        size_t base = ((size_t)b * 64 + f) * 2048 + (kb >> 1) + 8 * q;
        *reinterpret_cast<uint4*>(&gVH[base    ]) = make_uint4(h[0],h[1],h[2],h[3]);
        *reinterpret_cast<uint4*>(&gVH[base + 4]) = make_uint4(h[4],h[5],h[6],h[7]);
        *reinterpret_cast<uint4*>(&gVL[base    ]) = make_uint4(l[0],l[1],l[2],l[3]);
        *reinterpret_cast<uint4*>(&gVL[base + 4]) = make_uint4(l[4],l[5],l[6],l[7]);
    }
}

// ============================================================================
// Kernel 2: mma.sync bf16 flash, cp.async 2-stage pipeline, KT=64.
// grid (64, 4), 256 threads = 8 warps.
// Warp w: q rows 16*(w>>1)..+15, keys 32*(w&1)..+31 of each 64-key step.
// Stage layout (u32 idx): sKh=st*8192, sKl=+2048, sVh=+4096, sVl=+6144.
// ============================================================================
__device__ __forceinline__ void cp_fill(u32 sbase, int st, size_t rowbase, int j0,
                                        const u32* vh, const u32* vl, int t) {
    u32 dst = sbase + (u32)st * 32768u;
#pragma unroll
    for (int i = 0; i < 2; i++) {                       // K hi/lo: 64 keys x 128B
        int idx = t + 256 * i;
        int key = idx >> 3, c4 = (idx & 7) << 2;
        u32 off = ((u32)key * 32 + (u32)((c4 + 4 * key) & 31)) * 4u;
        size_t src = (rowbase + j0 + key) * 32 + c4;
        cp16(dst + off,         &gKH[src]);
        cp16(dst + 8192u + off, &gKL[src]);
    }
#pragma unroll
    for (int i = 0; i < 2; i++) {                       // V^T hi/lo: 64 f x 128B
        int idx = t + 256 * i;
        int f = idx >> 3, c4 = (idx & 7) << 2;
        u32 off = ((u32)f * 32 + (u32)((c4 + 4 * f) & 31)) * 4u;
        size_t src = (size_t)f * 2048 + (j0 >> 1) + c4;
        cp16(dst + 16384u + off, &vh[src]);
        cp16(dst + 24576u + off, &vl[src]);
    }
}

__global__ __launch_bounds__(256, 2) void flash_mma(
    const float* __restrict__ x, const float* __restrict__ W3,
    const float* __restrict__ b3, float* __restrict__ out) {
    u32* sm   = reinterpret_cast<u32*>(hx_smem);
    u32 sbase = smem_u32(hx_smem);

    int t = threadIdx.x, w = t >> 5, lane = t & 31;
    int gid = lane >> 2, tig = lane & 3;
    int r0  = (w >> 1) * 16;       // row group base (0..48)
    int ko  = (w & 1) * 32;        // key half offset within step
    int batch = blockIdx.y, m0 = blockIdx.x * MT;
    size_t rowbase = (size_t)batch * NTOK;

    const u32* vh = gVH + (size_t)batch * 64 * 2048;
    const u32* vl = gVL + (size_t)batch * 64 * 2048;

    // ---- persistent Q fragments (hi/lo), 4 k-chunks ----
    u32 qh[4][4], ql[4][4];
    {
        size_t ra = (rowbase + m0 + r0 + gid) * 32;
        size_t rb = ra + 8 * 32;
#pragma unroll
        for (int c = 0; c < 4; c++) {
            qh[c][0] = gKH[ra + 8*c + tig];     qh[c][1] = gKH[rb + 8*c + tig];
            qh[c][2] = gKH[ra + 8*c + 4 + tig]; qh[c][3] = gKH[rb + 8*c + 4 + tig];
            ql[c][0] = gKL[ra + 8*c + tig];     ql[c][1] = gKL[rb + 8*c + tig];
            ql[c][2] = gKL[ra + 8*c + 4 + tig]; ql[c][3] = gKL[rb + 8*c + 4 + tig];
        }
    }
    float m0r = g_m[rowbase + m0 + r0 + gid];
    float m1r = g_m[rowbase + m0 + r0 + gid + 8];
    float l0 = 0.f, l1 = 0.f;
    float O[8][4] = {};

    // ---- pipeline prologue ----
    cp_fill(sbase, 0, rowbase, 0, vh, vl, t);
    CP_COMMIT();

    for (int s = 0; s < NSTEP; s++) {
        if (s + 1 < NSTEP) {
            cp_fill(sbase, (s + 1) & 1, rowbase, (s + 1) * KT, vh, vl, t);
            CP_COMMIT();
            CP_WAIT(1);
        } else {
            CP_WAIT(0);
        }
        __syncthreads();

        const u32* sKh = sm + (s & 1) * 8192;
        const u32* sKl = sKh + 2048;
        const u32* sVh = sKh + 4096;
        const u32* sVl = sKh + 6144;

        // ---- GEMM1: S = QhKh + QhKl + QlKh ----
        float S[4][4] = {};
#pragma unroll
        for (int c = 0; c < 4; c++) {
#pragma unroll
            for (int nn = 0; nn < 4; nn++) {
                int key = ko + 8 * nn + gid;
                u32 base = (u32)key * 32;
                u32 p0 = base + (u32)((8*c     + tig + 4*key) & 31);
                u32 p1 = base + (u32)((8*c + 4 + tig + 4*key) & 31);
                u32 bh[2] = { sKh[p0], sKh[p1] };
                u32 bl[2] = { sKl[p0], sKl[p1] };
                mma16816(S[nn], qh[c], bh);
                mma16816(S[nn], qh[c], bl);
                mma16816(S[nn], ql[c], bh);
            }
        }
        // ---- softmax (fixed shift) ----
#pragma unroll
        for (int nn = 0; nn < 4; nn++) {
            float e0 = __expf(S[nn][0] - m0r), e1 = __expf(S[nn][1] - m0r);
            float e2 = __expf(S[nn][2] - m1r), e3 = __expf(S[nn][3] - m1r);
            l0 += e0 + e1; l1 += e2 + e3;
            S[nn][0] = e0; S[nn][1] = e1; S[nn][2] = e2; S[nn][3] = e3;
        }
        // ---- GEMM2: O += PhVh + PhVl + PlVh (2 k-chunks of 16 keys) ----
#pragma unroll
        for (int c = 0; c < 2; c++) {
            u32 ph[4], pl[4];
            {
                float a, b;
                a = S[2*c][0];   b = S[2*c][1];
                ph[0] = cvt2bf(a, b); pl[0] = cvt2bf(a - bflo(ph[0]), b - bfhi(ph[0]));
                a = S[2*c][2];   b = S[2*c][3];
                ph[1] = cvt2bf(a, b); pl[1] = cvt2bf(a - bflo(ph[1]), b - bfhi(ph[1]));
                a = S[2*c+1][0]; b = S[2*c+1][1];
                ph[2] = cvt2bf(a, b); pl[2] = cvt2bf(a - bflo(ph[2]), b - bfhi(ph[2]));
                a = S[2*c+1][2]; b = S[2*c+1][3];
                ph[3] = cvt2bf(a, b); pl[3] = cvt2bf(a - bflo(ph[3]), b - bfhi(ph[3]));
            }
            u32 jb = (u32)(ko >> 1) + 8u * (u32)c;     // keypair base in 32-wide tile
#pragma unroll
            for (int nn = 0; nn < 8; nn++) {
                int f = 8 * nn + gid;
                u32 base = (u32)f * 32;
                u32 p0 = base + ((jb + (u32)tig     + 4u * (u32)f) & 31);
                u32 p1 = base + ((jb + (u32)tig + 4 + 4u * (u32)f) & 31);
                u32 bh[2] = { sVh[p0], sVh[p1] };
                u32 bl[2] = { sVl[p0], sVl[p1] };
                mma16816(O[nn], ph, bh);
                mma16816(O[nn], ph, bl);
                mma16816(O[nn], pl, bh);
            }
        }
        __syncthreads();
    }

    // ===================== combine halves + epilogue =====================
    l0 += __shfl_xor_sync(0xffffffffu, l0, 1);
    l0 += __shfl_xor_sync(0xffffffffu, l0, 2);
    l1 += __shfl_xor_sync(0xffffffffu, l1, 1);
    l1 += __shfl_xor_sync(0xffffffffu, l1, 2);

    float* sO  = reinterpret_cast<float*>(hx_smem);   // [2][64][68]
    float* sLp = sO + 2 * 64 * 68;                    // [2][64]
    float* zT  = sLp + 128;                           // [64 f][68]
    float* wT  = zT + 64 * 68;                        // [64 f][68]

#pragma unroll
    for (int nn = 0; nn < 8; nn++) {
        int f = 8 * nn + 2 * tig;
        int rA = (w & 1) * 64 + r0 + gid;
        sO[rA * 68 + f]       = O[nn][0];
        sO[rA * 68 + f + 1]   = O[nn][1];
        sO[(rA+8) * 68 + f]   = O[nn][2];
        sO[(rA+8) * 68 + f+1] = O[nn][3];
    }
    if (tig == 0) {
        sLp[(w & 1) * 64 + r0 + gid]     = l0;
        sLp[(w & 1) * 64 + r0 + gid + 8] = l1;
    }
    __syncthreads();

    // z = 0.5*(O/l + x), stored transposed zT[f][row]
#pragma unroll
    for (int i = 0; i < 4; i++) {
        int idx = t + 256 * i;
        int row = idx >> 4, f4 = (idx & 15) << 2;
        float l   = sLp[row] + sLp[64 + row];
        float inv = 0.5f / l;
        float4 xv = *reinterpret_cast<const float4*>(&x[(rowbase + m0 + row) * 64 + f4]);
        float4 o0 = *reinterpret_cast<float4*>(&sO[row * 68 + f4]);
        float4 o1 = *reinterpret_cast<float4*>(&sO[(64 + row) * 68 + f4]);
        zT[(f4+0) * 68 + row] = (o0.x + o1.x) * inv + 0.5f * xv.x;
        zT[(f4+1) * 68 + row] = (o0.y + o1.y) * inv + 0.5f * xv.y;
        zT[(f4+2) * 68 + row] = (o0.z + o1.z) * inv + 0.5f * xv.z;
        zT[(f4+3) * 68 + row] = (o0.w + o1.w) * inv + 0.5f * xv.w;
    }
    load_tile_T(W3, wT);
    __syncthreads();

    // out = relu(Z @ W3^T + b3), SIMT 4x4 microtile over 64x64
    int ty = t >> 4, tx = t & 15;
    float acc[4][4] = {};
#pragma unroll 8
    for (int f = 0; f < 64; f++) {
        float4 zz = *reinterpret_cast<float4*>(&zT[f * 68 + 4 * ty]);
        float4 ww = *reinterpret_cast<float4*>(&wT[f * 68 + 4 * tx]);
        float zr[4] = {zz.x, zz.y, zz.z, zz.w};
        float wo[4] = {ww.x, ww.y, ww.z, ww.w};
#pragma unroll
        for (int r = 0; r < 4; r++)
#pragma unroll
            for (int o = 0; o < 4; o++) acc[r][o] = fmaf(zr[r], wo[o], acc[r][o]);
    }
    float4 bbv = *reinterpret_cast<const float4*>(&b3[4 * tx]);
#pragma unroll
    for (int r = 0; r < 4; r++) {
        float4 res = make_float4(fmaxf(acc[r][0] + bbv.x, 0.f),
                                 fmaxf(acc[r][1] + bbv.y, 0.f),
                                 fmaxf(acc[r][2] + bbv.z, 0.f),
                                 fmaxf(acc[r][3] + bbv.w, 0.f));
        *reinterpret_cast<float4*>(
            &out[(rowbase + m0 + 4 * ty + r) * 64 + 4 * tx]) = res;
    }
}

// ----------------------------------------------------------------------------
extern "C" void kernel_launch(void* const* d_in, const int* in_sizes, int n_in,
                              void* d_out, int out_size) {
    (void)in_sizes; (void)n_in; (void)out_size;
    const float* x  = (const float*)d_in[0];
    const float* W1 = (const float*)d_in[1];
    const float* b1 = (const float*)d_in[2];
    const float* W2 = (const float*)d_in[3];
    const float* b2 = (const float*)d_in[4];
    const float* W3 = (const float*)d_in[5];
    const float* b3 = (const float*)d_in[6];
    float* out = (float*)d_out;

    constexpr int P_SMEM     = (4 * 64 * LDT + 64) * (int)sizeof(float);
    constexpr int FLASH_SMEM = (2*64*68 + 128 + 2*64*68) * (int)sizeof(float); // 70144
    static bool done = false;
    if (!done) {
        cudaFuncSetAttribute(p_kernel,
            cudaFuncAttributeMaxDynamicSharedMemorySize, P_SMEM);
        cudaFuncSetAttribute(flash_mma,
            cudaFuncAttributeMaxDynamicSharedMemorySize, FLASH_SMEM);
        done = true;
    }
    p_kernel<<<BATCH * NTOK / 64, 256, P_SMEM>>>(x, W1, b1, W2, b2);
    flash_mma<<<dim3(NTOK / MT, BATCH), 256, FLASH_SMEM>>>(x, W3, b3, out);
}

// round 13
// speedup vs baseline: 3.6500x; 1.2094x over previous
#include <cuda_runtime.h>
#include <cuda_bf16.h>

using u32 = unsigned; using u64 = unsigned long long;

#define LDT 68
static constexpr int BATCH = 4, NTOK = 4096, MT = 64, KT = 64, NSTEP = NTOK / KT;

extern __shared__ char hx_smem[];

// ---- device scratch --------------------------------------------------------
// gK rows: 32 u32, PERMUTED: value j stored at pos (j&3)*8 + (j>>2)
__device__ u32   gKH[16384 * 32];
__device__ u32   gKL[16384 * 32];
// gV rows: 2048 u32; within each 32-u32 block: pos = 16*(i>>4) + (i&3)*4 + ((i&15)>>2)
__device__ u32   gVH[BATCH * 64 * 2048];
__device__ float g_m[BATCH * NTOK];

// ---- helpers -----------------------------------------------------------------
__device__ __forceinline__ u32 smem_u32(const void* p) {
    u32 a; asm("{ .reg .u64 t; cvta.to.shared.u64 t, %1; cvt.u32.u64 %0, t; }"
               : "=r"(a) : "l"(p)); return a;
}
__device__ __forceinline__ u32 cvt2bf(float lo, float hi) {
    u32 r; asm("cvt.rn.bf16x2.f32 %0, %1, %2;" : "=r"(r) : "f"(hi), "f"(lo)); return r;
}
__device__ __forceinline__ float bflo(u32 u) { return __uint_as_float(u << 16); }
__device__ __forceinline__ float bfhi(u32 u) { return __uint_as_float(u & 0xffff0000u); }

__device__ __forceinline__ void mma16816(float* d, const u32* a, const u32* b) {
    asm volatile(
        "mma.sync.aligned.m16n8k16.row.col.f32.bf16.bf16.f32 "
        "{%0,%1,%2,%3}, {%4,%5,%6,%7}, {%8,%9}, {%0,%1,%2,%3};"
        : "+f"(d[0]), "+f"(d[1]), "+f"(d[2]), "+f"(d[3])
        : "r"(a[0]), "r"(a[1]), "r"(a[2]), "r"(a[3]), "r"(b[0]), "r"(b[1]));
}
__device__ __forceinline__ void cp16(u32 dst, const void* src) {
    asm volatile("cp.async.cg.shared.global [%0], [%1], 16;"
                 :: "r"(dst), "l"(src) : "memory");
}
#define CP_COMMIT() asm volatile("cp.async.commit_group;" ::: "memory")
#define CP_WAIT(n)  asm volatile("cp.async.wait_group %0;" :: "n"(n) : "memory")

// fp32 packed helpers (p_kernel)
__device__ __forceinline__ u64 pk2(float x, float y) {
    u64 r; asm("mov.b64 %0, {%1, %2};" : "=l"(r) : "f"(x), "f"(y)); return r;
}
__device__ __forceinline__ u64 dup2(float x) {
    u64 r; asm("mov.b64 %0, {%1, %1};" : "=l"(r) : "f"(x)); return r;
}
__device__ __forceinline__ void fma2(u64& d, u64 a, u64 b) {
    asm("fma.rn.f32x2 %0, %1, %2, %0;" : "+l"(d) : "l"(a), "l"(b));
}
__device__ __forceinline__ float2 up2(u64 v) {
    float2 f; asm("mov.b64 {%0, %1}, %2;" : "=f"(f.x), "=f"(f.y) : "l"(v)); return f;
}

// ---- fp32 64x64 tile loaders ---------------------------------------------------
__device__ __forceinline__ void load_tile_T(const float* __restrict__ g, float* s) {
    int t = threadIdx.x;
#pragma unroll
    for (int i = 0; i < 4; i++) {
        int idx = t + i * 256, n = idx >> 4, k4 = (idx & 15) << 2;
        float4 v = *reinterpret_cast<const float4*>(g + n * 64 + k4);
        s[(k4+0)*LDT+n] = v.x; s[(k4+1)*LDT+n] = v.y;
        s[(k4+2)*LDT+n] = v.z; s[(k4+3)*LDT+n] = v.w;
    }
}
__device__ __forceinline__ void load_tile_N(const float* __restrict__ g, float* s) {
    int t = threadIdx.x;
#pragma unroll
    for (int i = 0; i < 4; i++) {
        int idx = t + i * 256, n = idx >> 4, k4 = (idx & 15) << 2;
        *reinterpret_cast<float4*>(s + n * LDT + k4) =
            *reinterpret_cast<const float4*>(g + n * 64 + k4);
    }
}

// ============================================================================
// Kernel 1: Weff/beff + p = x@Weff^T + beff; emit permuted p hi/lo, permuted
// x^T hi, g_m = |p_row|^2.
// ============================================================================
__global__ __launch_bounds__(256) void p_kernel(
    const float* __restrict__ x,
    const float* __restrict__ W1, const float* __restrict__ b1,
    const float* __restrict__ W2, const float* __restrict__ b2) {
    float* smem = reinterpret_cast<float*>(hx_smem);
    float* sXT  = smem;
    float* sWT  = sXT  + 64 * LDT;
    float* sW1  = sWT  + 64 * LDT;
    float* sW2T = sW1  + 64 * LDT;
    float* sB1  = sW2T + 64 * LDT;

    int n0 = blockIdx.x * 64;
    load_tile_T(x + (size_t)n0 * 64, sXT);
    load_tile_N(W1, sW1);
    load_tile_T(W2, sW2T);
    int t = threadIdx.x;
    if (t < 64) sB1[t] = b1[t];
    __syncthreads();

    int ty = t >> 4, tx = t & 15;

    u64 aw[4][2] = {};
#pragma unroll 16
    for (int k = 0; k < 64; k++) {
        float4 a = *reinterpret_cast<float4*>(&sW2T[k * LDT + 4 * tx]);
        float4 b = *reinterpret_cast<float4*>(&sW1 [k * LDT + 4 * ty]);
        u64 a01 = pk2(a.x, a.y), a23 = pk2(a.z, a.w), d;
        d = dup2(b.x); fma2(aw[0][0], a01, d); fma2(aw[0][1], a23, d);
        d = dup2(b.y); fma2(aw[1][0], a01, d); fma2(aw[1][1], a23, d);
        d = dup2(b.z); fma2(aw[2][0], a01, d); fma2(aw[2][1], a23, d);
        d = dup2(b.w); fma2(aw[3][0], a01, d); fma2(aw[3][1], a23, d);
    }
    float be[4];
    {
        float4 bv = *reinterpret_cast<const float4*>(&b2[4 * tx]);
        be[0]=bv.x; be[1]=bv.y; be[2]=bv.z; be[3]=bv.w;
#pragma unroll 16
        for (int k = 0; k < 64; k++) {
            float4 w = *reinterpret_cast<float4*>(&sW2T[k * LDT + 4 * tx]);
            float bk = sB1[k];
            be[0]=fmaf(w.x,bk,be[0]); be[1]=fmaf(w.y,bk,be[1]);
            be[2]=fmaf(w.z,bk,be[2]); be[3]=fmaf(w.w,bk,be[3]);
        }
    }
#pragma unroll
    for (int jj = 0; jj < 4; jj++) {
        float2 lo = up2(aw[jj][0]), hi = up2(aw[jj][1]);
        *reinterpret_cast<float4*>(&sWT[(4*ty+jj)*LDT + 4*tx]) =
            make_float4(lo.x, lo.y, hi.x, hi.y);
    }
    __syncthreads();

    u64 acc[4][2] = {};
#pragma unroll 16
    for (int j = 0; j < 64; j++) {
        float4 a = *reinterpret_cast<float4*>(&sXT[j * LDT + 4 * ty]);
        float4 b = *reinterpret_cast<float4*>(&sWT[j * LDT + 4 * tx]);
        u64 b01 = pk2(b.x, b.y), b23 = pk2(b.z, b.w), d;
        d = dup2(a.x); fma2(acc[0][0], d, b01); fma2(acc[0][1], d, b23);
        d = dup2(a.y); fma2(acc[1][0], d, b01); fma2(acc[1][1], d, b23);
        d = dup2(a.z); fma2(acc[2][0], d, b01); fma2(acc[2][1], d, b23);
        d = dup2(a.w); fma2(acc[3][0], d, b01); fma2(acc[3][1], d, b23);
    }
    // K write: value u32 j stored at pos (j&3)*8 + (j>>2).
    // j = 2tx  -> 16*(tx&1) + (tx>>1);  j = 2tx+1 -> +8.
    int kp0 = 16 * (tx & 1) + (tx >> 1);
#pragma unroll
    for (int r = 0; r < 4; r++) {
        float2 lo = up2(acc[r][0]), hi = up2(acc[r][1]);
        float p0 = lo.x+be[0], p1 = lo.y+be[1], p2 = hi.x+be[2], p3 = hi.y+be[3];
        int row = n0 + 4 * ty + r;
        u32 h01 = cvt2bf(p0, p1), h23 = cvt2bf(p2, p3);
        u32 l01 = cvt2bf(p0 - bflo(h01), p1 - bfhi(h01));
        u32 l23 = cvt2bf(p2 - bflo(h23), p3 - bfhi(h23));
        size_t rb = (size_t)row * 32;
        gKH[rb + kp0]     = h01;  gKH[rb + kp0 + 8] = h23;
        gKL[rb + kp0]     = l01;  gKL[rb + kp0 + 8] = l23;
        float msq = p0*p0 + p1*p1 + p2*p2 + p3*p3;
#pragma unroll
        for (int off = 8; off; off >>= 1)
            msq += __shfl_xor_sync(0xffffffffu, msq, off);
        if (tx == 0) g_m[row] = msq;
    }

    // x^T hi -> gVH, permuted within each 32-u32 block
    {
        int b  = n0 >> 12, kb = n0 & 4095;
        int f  = t >> 2, q = t & 3;
        const float* src = &sXT[f * LDT + 16 * q];
        size_t base = ((size_t)b * 64 + f) * 2048 + (kb >> 1);
#pragma unroll
        for (int r = 0; r < 8; r++) {
            float v0 = src[2*r], v1 = src[2*r+1];
            u32 h = cvt2bf(v0, v1);
            // i = 8q + r; pos = 16*(i>>4) + ((i&3)*4) + ((i&15)>>2)
            int i = 8 * q + r;
            int pos = 16 * (i >> 4) + (i & 3) * 4 + ((i & 15) >> 2);
            gVH[base + pos] = h;
        }
    }
}

// ============================================================================
// Kernel 2: mma.sync bf16 flash, 3-stage cp.async pipeline, LDS.128 b-frags.
// Stage (u32): sKh = st*6144, sKl = +2048, sVh = +4096 (24 KB/stage).
// ============================================================================
static constexpr u32 STAGE_U32 = 6144;

__device__ __forceinline__ void cp_fill(u32 sbase, int st, size_t rowbase, int j0,
                                        const u32* vh, int t) {
    u32 dst = sbase + (u32)st * (STAGE_U32 * 4u);
#pragma unroll
    for (int i = 0; i < 2; i++) {                 // K hi+lo: 64 keys x 8 chunks
        int idx = t + 256 * i;
        int key = idx >> 3, k = idx & 7;
        u32 off = (u32)key * 128u + (u32)((k ^ (key & 7)) * 16);
        size_t src = (rowbase + j0 + key) * 32 + 4 * k;
        cp16(dst + off,         &gKH[src]);
        cp16(dst + 8192u + off, &gKL[src]);
    }
#pragma unroll
    for (int i = 0; i < 2; i++) {                 // V hi: 64 f x 8 chunks
        int idx = t + 256 * i;
        int f = idx >> 3, k = idx & 7;
        u32 rho = (u32)(((f & 1) << 2) | ((f & 7) >> 1));
        u32 off = 16384u + (u32)f * 128u + (u32)((k ^ rho) * 16);
        cp16(dst + off, &vh[(size_t)f * 2048 + (j0 >> 1) + 4 * k]);
    }
}

__global__ __launch_bounds__(256, 2) void flash_mma(
    const float* __restrict__ x, const float* __restrict__ W3,
    const float* __restrict__ b3, float* __restrict__ out) {
    u32 sbase = smem_u32(hx_smem);
    const uint4* smu4 = reinterpret_cast<const uint4*>(hx_smem);

    int t = threadIdx.x, w = t >> 5, lane = t & 31;
    int gid = lane >> 2, tig = lane & 3;
    int r0  = (w >> 1) * 16;
    int ko  = (w & 1) * 32;
    int batch = blockIdx.y, m0 = blockIdx.x * MT;
    size_t rowbase = (size_t)batch * NTOK;
    const u32* vh = gVH + (size_t)batch * 64 * 2048;

    // per-thread constant chunk ids
    u32 cA    = (u32)((2 * tig) ^ gid);          // K chunk (c0,c1)
    u32 cB    = cA ^ 1u;                          // K chunk (c2,c3)
    u32 rho   = (u32)(((gid & 1) << 2) | (gid >> 1));
    u32 vphys = (u32)((w & 1) * 4 + tig) ^ rho;   // V chunk (both c)

    // ---- persistent Q fragments from permuted gK: 2 uint4 per row per buf ----
    u32 qh[4][4], ql[4][4];
    {
        size_t ra = (rowbase + m0 + r0 + gid) * 32 + 8 * tig;
        size_t rb = ra + 8 * 32;
        uint4 A0 = *reinterpret_cast<const uint4*>(&gKH[ra]);
        uint4 A1 = *reinterpret_cast<const uint4*>(&gKH[ra + 4]);
        uint4 B0 = *reinterpret_cast<const uint4*>(&gKH[rb]);
        uint4 B1 = *reinterpret_cast<const uint4*>(&gKH[rb + 4]);
        qh[0][0]=A0.x; qh[0][1]=B0.x; qh[0][2]=A0.y; qh[0][3]=B0.y;
        qh[1][0]=A0.z; qh[1][1]=B0.z; qh[1][2]=A0.w; qh[1][3]=B0.w;
        qh[2][0]=A1.x; qh[2][1]=B1.x; qh[2][2]=A1.y; qh[2][3]=B1.y;
        qh[3][0]=A1.z; qh[3][1]=B1.z; qh[3][2]=A1.w; qh[3][3]=B1.w;
        A0 = *reinterpret_cast<const uint4*>(&gKL[ra]);
        A1 = *reinterpret_cast<const uint4*>(&gKL[ra + 4]);
        B0 = *reinterpret_cast<const uint4*>(&gKL[rb]);
        B1 = *reinterpret_cast<const uint4*>(&gKL[rb + 4]);
        ql[0][0]=A0.x; ql[0][1]=B0.x; ql[0][2]=A0.y; ql[0][3]=B0.y;
        ql[1][0]=A0.z; ql[1][1]=B0.z; ql[1][2]=A0.w; ql[1][3]=B0.w;
        ql[2][0]=A1.x; ql[2][1]=B1.x; ql[2][2]=A1.y; ql[2][3]=B1.y;
        ql[3][0]=A1.z; ql[3][1]=B1.z; ql[3][2]=A1.w; ql[3][3]=B1.w;
    }
    float m0r = g_m[rowbase + m0 + r0 + gid];
    float m1r = g_m[rowbase + m0 + r0 + gid + 8];
    float l0 = 0.f, l1 = 0.f;
    float O[8][4] = {};

    // ---- pipeline prologue: fill stages 0,1 ----
    cp_fill(sbase, 0, rowbase, 0, vh, t); CP_COMMIT();
    cp_fill(sbase, 1, rowbase, KT, vh, t); CP_COMMIT();

    for (int s = 0; s < NSTEP; s++) {
        if (s == NSTEP - 1) { CP_WAIT(0); } else { CP_WAIT(1); }
        __syncthreads();
        if (s + 2 < NSTEP) {
            cp_fill(sbase, (s + 2) % 3, rowbase, (s + 2) * KT, vh, t);
            CP_COMMIT();
        }
        const uint4* stK = smu4 + (size_t)(s % 3) * (STAGE_U32 / 4);
        const uint4* stKl = stK + 512;     // +2048 u32
        const uint4* stV  = stK + 1024;    // +4096 u32

        // ---- GEMM1: S = QhKh + QhKl + QlKh ----
        float S[4][4] = {};
#pragma unroll
        for (int nn = 0; nn < 4; nn++) {
            int key = ko + 8 * nn + gid;
            uint4 HA = stK [key * 8 + cA], HB = stK [key * 8 + cB];
            uint4 LA = stKl[key * 8 + cA], LB = stKl[key * 8 + cB];
            u32 bh[2], bl[2];
            bh[0]=HA.x; bh[1]=HA.y; bl[0]=LA.x; bl[1]=LA.y;   // c0
            mma16816(S[nn], qh[0], bh); mma16816(S[nn], qh[0], bl);
            mma16816(S[nn], ql[0], bh);
            bh[0]=HA.z; bh[1]=HA.w; bl[0]=LA.z; bl[1]=LA.w;   // c1
            mma16816(S[nn], qh[1], bh); mma16816(S[nn], qh[1], bl);
            mma16816(S[nn], ql[1], bh);
            bh[0]=HB.x; bh[1]=HB.y; bl[0]=LB.x; bl[1]=LB.y;   // c2
            mma16816(S[nn], qh[2], bh); mma16816(S[nn], qh[2], bl);
            mma16816(S[nn], ql[2], bh);
            bh[0]=HB.z; bh[1]=HB.w; bl[0]=LB.z; bl[1]=LB.w;   // c3
            mma16816(S[nn], qh[3], bh); mma16816(S[nn], qh[3], bl);
            mma16816(S[nn], ql[3], bh);
        }
        // ---- softmax (fixed shift) ----
#pragma unroll
        for (int nn = 0; nn < 4; nn++) {
            float e0 = __expf(S[nn][0] - m0r), e1 = __expf(S[nn][1] - m0r);
            float e2 = __expf(S[nn][2] - m1r), e3 = __expf(S[nn][3] - m1r);
            l0 += e0 + e1; l1 += e2 + e3;
            S[nn][0] = e0; S[nn][1] = e1; S[nn][2] = e2; S[nn][3] = e3;
        }
        // ---- P fragments for both c (hi + lo) ----
        u32 ph[2][4], pl[2][4];
#pragma unroll
        for (int c = 0; c < 2; c++) {
            float a, b;
            a = S[2*c][0];   b = S[2*c][1];
            ph[c][0] = cvt2bf(a, b); pl[c][0] = cvt2bf(a - bflo(ph[c][0]), b - bfhi(ph[c][0]));
            a = S[2*c][2];   b = S[2*c][3];
            ph[c][1] = cvt2bf(a, b); pl[c][1] = cvt2bf(a - bflo(ph[c][1]), b - bfhi(ph[c][1]));
            a = S[2*c+1][0]; b = S[2*c+1][1];
            ph[c][2] = cvt2bf(a, b); pl[c][2] = cvt2bf(a - bflo(ph[c][2]), b - bfhi(ph[c][2]));
            a = S[2*c+1][2]; b = S[2*c+1][3];
            ph[c][3] = cvt2bf(a, b); pl[c][3] = cvt2bf(a - bflo(ph[c][3]), b - bfhi(ph[c][3]));
        }
        // ---- GEMM2: O += PhVh + PlVh (V hi only) ----
#pragma unroll
        for (int nn = 0; nn < 8; nn++) {
            int f = 8 * nn + gid;
            uint4 VA = stV[f * 8 + vphys];   // (c0 b0, c0 b1, c1 b0, c1 b1)
            u32 bv[2];
            bv[0] = VA.x; bv[1] = VA.y;
            mma16816(O[nn], ph[0], bv); mma16816(O[nn], pl[0], bv);
            bv[0] = VA.z; bv[1] = VA.w;
            mma16816(O[nn], ph[1], bv); mma16816(O[nn], pl[1], bv);
        }
    }

    // ===================== combine halves + epilogue =====================
    l0 += __shfl_xor_sync(0xffffffffu, l0, 1);
    l0 += __shfl_xor_sync(0xffffffffu, l0, 2);
    l1 += __shfl_xor_sync(0xffffffffu, l1, 1);
    l1 += __shfl_xor_sync(0xffffffffu, l1, 2);

    __syncthreads();
    float* sO  = reinterpret_cast<float*>(hx_smem);   // [2][64][68]
    float* sLp = sO + 2 * 64 * 68;                    // [2][64]
    float* zT  = sLp + 128;                           // [64 f][68]
    float* wT  = zT + 64 * 68;                        // [64 f][68]

#pragma unroll
    for (int nn = 0; nn < 8; nn++) {
        int f = 8 * nn + 2 * tig;
        int rA = (w & 1) * 64 + r0 + gid;
        sO[rA * 68 + f]       = O[nn][0];
        sO[rA * 68 + f + 1]   = O[nn][1];
        sO[(rA+8) * 68 + f]   = O[nn][2];
        sO[(rA+8) * 68 + f+1] = O[nn][3];
    }
    if (tig == 0) {
        sLp[(w & 1) * 64 + r0 + gid]     = l0;
        sLp[(w & 1) * 64 + r0 + gid + 8] = l1;
    }
    __syncthreads();

#pragma unroll
    for (int i = 0; i < 4; i++) {
        int idx = t + 256 * i;
        int row = idx >> 4, f4 = (idx & 15) << 2;
        float l   = sLp[row] + sLp[64 + row];
        float inv = 0.5f / l;
        float4 xv = *reinterpret_cast<const float4*>(&x[(rowbase + m0 + row) * 64 + f4]);
        float4 o0 = *reinterpret_cast<float4*>(&sO[row * 68 + f4]);
        float4 o1 = *reinterpret_cast<float4*>(&sO[(64 + row) * 68 + f4]);
        zT[(f4+0) * 68 + row] = (o0.x + o1.x) * inv + 0.5f * xv.x;
        zT[(f4+1) * 68 + row] = (o0.y + o1.y) * inv + 0.5f * xv.y;
        zT[(f4+2) * 68 + row] = (o0.z + o1.z) * inv + 0.5f * xv.z;
        zT[(f4+3) * 68 + row] = (o0.w + o1.w) * inv + 0.5f * xv.w;
    }
    load_tile_T(W3, wT);
    __syncthreads();

    int ty = t >> 4, tx = t & 15;
    float acc[4][4] = {};
#pragma unroll 8
    for (int f = 0; f < 64; f++) {
        float4 zz = *reinterpret_cast<float4*>(&zT[f * 68 + 4 * ty]);
        float4 ww = *reinterpret_cast<float4*>(&wT[f * 68 + 4 * tx]);
        float zr[4] = {zz.x, zz.y, zz.z, zz.w};
        float wo[4] = {ww.x, ww.y, ww.z, ww.w};
#pragma unroll
        for (int r = 0; r < 4; r++)
#pragma unroll
            for (int o = 0; o < 4; o++) acc[r][o] = fmaf(zr[r], wo[o], acc[r][o]);
    }
    float4 bbv = *reinterpret_cast<const float4*>(&b3[4 * tx]);
#pragma unroll
    for (int r = 0; r < 4; r++) {
        float4 res = make_float4(fmaxf(acc[r][0] + bbv.x, 0.f),
                                 fmaxf(acc[r][1] + bbv.y, 0.f),
                                 fmaxf(acc[r][2] + bbv.z, 0.f),
                                 fmaxf(acc[r][3] + bbv.w, 0.f));
        *reinterpret_cast<float4*>(
            &out[(rowbase + m0 + 4 * ty + r) * 64 + 4 * tx]) = res;
    }
}

// ----------------------------------------------------------------------------
extern "C" void kernel_launch(void* const* d_in, const int* in_sizes, int n_in,
                              void* d_out, int out_size) {
    (void)in_sizes; (void)n_in; (void)out_size;
    const float* x  = (const float*)d_in[0];
    const float* W1 = (const float*)d_in[1];
    const float* b1 = (const float*)d_in[2];
    const float* W2 = (const float*)d_in[3];
    const float* b2 = (const float*)d_in[4];
    const float* W3 = (const float*)d_in[5];
    const float* b3 = (const float*)d_in[6];
    float* out = (float*)d_out;

    constexpr int P_SMEM     = (4 * 64 * LDT + 64) * (int)sizeof(float);
    constexpr int FLASH_SMEM = 3 * 24576;   // 73728 >= epilogue overlay 70144
    static bool done = false;
    if (!done) {
        cudaFuncSetAttribute(p_kernel,
            cudaFuncAttributeMaxDynamicSharedMemorySize, P_SMEM);
        cudaFuncSetAttribute(flash_mma,
            cudaFuncAttributeMaxDynamicSharedMemorySize, FLASH_SMEM);
        done = true;
    }
    p_kernel<<<BATCH * NTOK / 64, 256, P_SMEM>>>(x, W1, b1, W2, b2);
    flash_mma<<<dim3(NTOK / MT, BATCH), 256, FLASH_SMEM>>>(x, W3, b3, out);
}